// round 1
// baseline (speedup 1.0000x reference)
#include <cuda_runtime.h>
#include <cuda_bf16.h>
#include <cstdint>

#define N_NODES 100000
#define N_EDGES 1600000
#define D_IN    128
#define D_OUT   64

// Scratch for support = X @ W  (25.6 MB). Static device array: no allocs allowed.
__device__ float g_support[(size_t)N_NODES * D_OUT];

// ---------------------------------------------------------------------------
// Kernel 1: support = X @ W   (fp32, FMA-bound)
// Block: 256 threads (8 warps). Each warp computes 4 node rows; lane l owns
// output cols l and l+32. W is staged transposed in shared with +4 padding so
// LDS.128 reads are bank-conflict free.
// Grid: 3125 blocks * 32 nodes/block = 100000 exactly.
// ---------------------------------------------------------------------------
__global__ __launch_bounds__(256) void gcn_gemm_kernel(
    const float* __restrict__ X, const float* __restrict__ W)
{
    __shared__ float WsT[D_OUT][D_IN + 4];   // 64 x 132 floats = 33792 B

    const int tid = threadIdx.x;
    // Load W [k][c] row-major -> WsT[c][k]
    for (int i = tid; i < D_IN * D_OUT; i += 256) {
        int k = i >> 6;      // / D_OUT
        int c = i & 63;      // % D_OUT
        WsT[c][k] = W[i];
    }
    __syncthreads();

    const int warp = tid >> 5;
    const int lane = tid & 31;
    const int nodeBase = (blockIdx.x * 8 + warp) * 4;
    if (nodeBase >= N_NODES) return;

    const float4* __restrict__ X4 = reinterpret_cast<const float4*>(X);

    float acc0[4] = {0.f, 0.f, 0.f, 0.f};
    float acc1[4] = {0.f, 0.f, 0.f, 0.f};

    #pragma unroll 4
    for (int k = 0; k < D_IN; k += 4) {
        const float4 w0 = *reinterpret_cast<const float4*>(&WsT[lane][k]);
        const float4 w1 = *reinterpret_cast<const float4*>(&WsT[lane + 32][k]);
        #pragma unroll
        for (int j = 0; j < 4; j++) {
            const int n = nodeBase + j;
            const float4 x = X4[(size_t)n * (D_IN / 4) + (k >> 2)];
            acc0[j] = fmaf(x.x, w0.x, acc0[j]);
            acc0[j] = fmaf(x.y, w0.y, acc0[j]);
            acc0[j] = fmaf(x.z, w0.z, acc0[j]);
            acc0[j] = fmaf(x.w, w0.w, acc0[j]);
            acc1[j] = fmaf(x.x, w1.x, acc1[j]);
            acc1[j] = fmaf(x.y, w1.y, acc1[j]);
            acc1[j] = fmaf(x.z, w1.z, acc1[j]);
            acc1[j] = fmaf(x.w, w1.w, acc1[j]);
        }
    }

    #pragma unroll
    for (int j = 0; j < 4; j++) {
        const int n = nodeBase + j;
        g_support[(size_t)n * D_OUT + lane]      = acc0[j];
        g_support[(size_t)n * D_OUT + lane + 32] = acc1[j];
    }
}

// ---------------------------------------------------------------------------
// Kernel 2: out[i][:] = bias  (vectorized float4)
// ---------------------------------------------------------------------------
__global__ __launch_bounds__(256) void gcn_init_kernel(
    float4* __restrict__ out4, const float4* __restrict__ bias4)
{
    const int i = blockIdx.x * 256 + threadIdx.x;
    if (i < N_NODES * (D_OUT / 4)) {
        out4[i] = bias4[i & 15];   // D_OUT/4 = 16 float4 per row
    }
}

// ---------------------------------------------------------------------------
// Kernel 3: scatter  out[row[e]] += val[e] * support[col[e]]
// 16 threads per edge, each owns one float4 chunk of the 64-wide row.
// Gather from support is fully coalesced (256 B/edge, mostly L2-resident),
// reduction via red.global.add.v4.f32 (no return value -> no scoreboard stall).
// ---------------------------------------------------------------------------
__global__ __launch_bounds__(256) void gcn_scatter_kernel(
    const int*   __restrict__ row,
    const int*   __restrict__ col,
    const float* __restrict__ val,
    const float4* __restrict__ support4,
    float* __restrict__ out)
{
    const long long idx = (long long)blockIdx.x * 256 + threadIdx.x;
    const long long e = idx >> 4;
    if (e >= N_EDGES) return;
    const int c = (int)(idx & 15);

    const int   r  = __ldg(row + e);
    const int   cc = __ldg(col + e);
    const float v  = __ldg(val + e);

    const float4 s = support4[(size_t)cc * (D_OUT / 4) + c];

    const float a0 = s.x * v;
    const float a1 = s.y * v;
    const float a2 = s.z * v;
    const float a3 = s.w * v;

    float* dst = out + (size_t)r * D_OUT + c * 4;
    asm volatile("red.global.add.v4.f32 [%0], {%1, %2, %3, %4};"
                 :: "l"(dst), "f"(a0), "f"(a1), "f"(a2), "f"(a3)
                 : "memory");
}

// ---------------------------------------------------------------------------
// Launch
// Inputs (metadata order): input_feature f32[100000,128], weight f32[128,64],
// bias f32[64], adj_row i32[1.6M], adj_col i32[1.6M], adj_val f32[1.6M]
// Output: f32[100000,64]
// ---------------------------------------------------------------------------
extern "C" void kernel_launch(void* const* d_in, const int* in_sizes, int n_in,
                              void* d_out, int out_size)
{
    const float* X    = (const float*)d_in[0];
    const float* W    = (const float*)d_in[1];
    const float* bias = (const float*)d_in[2];
    const int*   arow = (const int*)d_in[3];
    const int*   acol = (const int*)d_in[4];
    const float* aval = (const float*)d_in[5];
    float* out = (float*)d_out;

    float* support = nullptr;
    cudaGetSymbolAddress((void**)&support, g_support);

    // 1) support = X @ W
    gcn_gemm_kernel<<<(N_NODES + 31) / 32, 256>>>(X, W);

    // 2) out = bias (broadcast)
    {
        const int total = N_NODES * (D_OUT / 4);
        gcn_init_kernel<<<(total + 255) / 256, 256>>>(
            (float4*)out, (const float4*)bias);
    }

    // 3) scatter-add over edges
    {
        const long long total = (long long)N_EDGES * 16;
        const int blocks = (int)((total + 255) / 256);
        gcn_scatter_kernel<<<blocks, 256>>>(
            arow, acol, aval, (const float4*)support, out);
    }
}